// round 14
// baseline (speedup 1.0000x reference)
#include <cuda_runtime.h>
#include <cuda_fp16.h>

// ---------------------------------------------------------------------------
// DummyGAT: h = x@W; GAT edge softmax + aggregation; out = mean(relu(agg)@W_lin + b_lin)
// N = 100000 nodes, E = 1.6M edges, IN=128, HID=64, OUT=64
// 5 launches: [gemm+hist+zero] -> [scan] -> [scatter(e,denom)] -> [edge RED] -> [finish]
// Scatter precomputes per-edge exp and the softmax denominator; the edge pass
// is a pure vector-load + run-dedup + red.v4 stream (no MUFU, no scalar loads).
// ---------------------------------------------------------------------------

#define N_MAX 100000
#define E_MAX 1600000
#define SCAN_BLOCKS 391   // ceil(100000/256)

__device__ __align__(256) __half g_h2[N_MAX * 64];    // h in fp16 (gather operand)
__device__ __align__(256) float  g_asrc[N_MAX];
__device__ __align__(256) float  g_adst[N_MAX];
__device__ __align__(256) float  g_agg[N_MAX * 64];   // edge-sum accumulator (zeroed in K1)
__device__ __align__(256) float  g_denom[N_MAX];      // edge exp-sum (zeroed in K1, filled by scatter)
__device__ __align__(256) int    g_deg[N_MAX];        // in-degree (zeroed by finish)
__device__ __align__(256) int    g_cursor[N_MAX];     // scan result / scatter cursor
__device__ __align__(256) int2   g_cedge[E_MAX];      // CSR slot: (src, dst)
__device__ __align__(256) float  g_e[E_MAX];          // CSR slot: exp(lrelu(logit))
__device__ __align__(256) unsigned long long g_pkt[SCAN_BLOCKS]; // lookback, zeroed by scatter
__device__ __align__(256) float  g_smulti[64 * 64];   // spread node-sum slots (zeroed by finish)
__device__ int g_done;                                // zeroed by finish

__device__ __forceinline__ float lrelu(float x) { return x > 0.f ? x : 0.2f * x; }

// ---------------------------------------------------------------------------
// Kernel 1: three block partitions.
//  [0,GB): h = x@W + attention scores (k-major x tile -> FFMA-bound)
//  [GB,GB+HB): in-degree histogram
//  [GB+HB,..): zero g_agg and g_denom (float4 streams, hidden under gemm)
// ---------------------------------------------------------------------------
__global__ void gemm_hist_zero_kernel(const float* __restrict__ x, const float* __restrict__ W,
                                      const float* __restrict__ att_src, const float* __restrict__ att_dst,
                                      const int* __restrict__ ei, int N, int E, int GB, int HB) {
    if (blockIdx.x >= GB + HB) {          // ---- zero partition ----
        int i = (blockIdx.x - GB - HB) * 256 + threadIdx.x;
        int nAgg = N * 16;                // g_agg in float4 units
        if (i < nAgg) ((float4*)g_agg)[i] = make_float4(0.f, 0.f, 0.f, 0.f);
        else if (i - nAgg < N / 4) ((float4*)g_denom)[i - nAgg] = make_float4(0.f, 0.f, 0.f, 0.f);
        return;
    }
    if (blockIdx.x >= GB) {               // ---- histogram partition ----
        int i = (blockIdx.x - GB) * 256 + threadIdx.x;
        if (i < E) atomicAdd(&g_deg[ei[E + i]], 1);
        return;
    }
    // ---- gemm partition ----
    int row0 = blockIdx.x * 64;

    __shared__ float xs[64 * 68];    // k-major: xs[k*68 + r]
    __shared__ float ws[64 * 64];    // [k][c]
    int tx = threadIdx.x & 15;       // col group (4 cols)
    int ty = threadIdx.x >> 4;       // row group (4 rows)
    float acc[4][4] = {};

    for (int k0 = 0; k0 < 128; k0 += 64) {
        #pragma unroll
        for (int i = 0; i < 4; i++) {
            int idx = threadIdx.x + i * 256;
            int r = idx >> 4, c4 = idx & 15;
            int grow = row0 + r;
            float4 v = make_float4(0.f, 0.f, 0.f, 0.f);
            if (grow < N) v = ((const float4*)x)[grow * 32 + (k0 >> 2) + c4];
            int kk = c4 * 4;
            xs[(kk + 0) * 68 + r] = v.x;
            xs[(kk + 1) * 68 + r] = v.y;
            xs[(kk + 2) * 68 + r] = v.z;
            xs[(kk + 3) * 68 + r] = v.w;
        }
        #pragma unroll
        for (int i = 0; i < 4; i++) {
            int idx = threadIdx.x + i * 256;
            ((float4*)ws)[idx] = ((const float4*)(W + k0 * 64))[idx];
        }
        __syncthreads();

        #pragma unroll 16
        for (int k = 0; k < 64; k++) {
            float4 xv = *(float4*)&xs[k * 68 + ty * 4];   // broadcast: 2 addrs/warp
            float4 wv = *(float4*)&ws[k * 64 + tx * 4];
            acc[0][0] += xv.x * wv.x; acc[0][1] += xv.x * wv.y; acc[0][2] += xv.x * wv.z; acc[0][3] += xv.x * wv.w;
            acc[1][0] += xv.y * wv.x; acc[1][1] += xv.y * wv.y; acc[1][2] += xv.y * wv.z; acc[1][3] += xv.y * wv.w;
            acc[2][0] += xv.z * wv.x; acc[2][1] += xv.z * wv.y; acc[2][2] += xv.z * wv.z; acc[2][3] += xv.z * wv.w;
            acc[3][0] += xv.w * wv.x; acc[3][1] += xv.w * wv.y; acc[3][2] += xv.w * wv.z; acc[3][3] += xv.w * wv.w;
        }
        __syncthreads();
    }

    // attention scores via width-16 shuffle reduce
    float4 as4 = ((const float4*)att_src)[tx];
    float4 ad4 = ((const float4*)att_dst)[tx];
    #pragma unroll
    for (int i = 0; i < 4; i++) {
        float pa = acc[i][0] * as4.x + acc[i][1] * as4.y + acc[i][2] * as4.z + acc[i][3] * as4.w;
        float pd = acc[i][0] * ad4.x + acc[i][1] * ad4.y + acc[i][2] * ad4.z + acc[i][3] * ad4.w;
        #pragma unroll
        for (int off = 8; off; off >>= 1) {
            pa += __shfl_down_sync(0xffffffffu, pa, off, 16);
            pd += __shfl_down_sync(0xffffffffu, pd, off, 16);
        }
        if (tx == 0) {
            int r = row0 + ty * 4 + i;
            if (r < N) { g_asrc[r] = pa; g_adst[r] = pd; }
        }
    }

    #pragma unroll
    for (int i = 0; i < 4; i++) {
        int r = row0 + ty * 4 + i;
        if (r >= N) continue;
        union { __half2 h[2]; float2 f; } u;
        u.h[0] = __floats2half2_rn(acc[i][0], acc[i][1]);
        u.h[1] = __floats2half2_rn(acc[i][2], acc[i][3]);
        ((float2*)g_h2)[r * 16 + tx] = u.f;
    }
}

// ---------------------------------------------------------------------------
// Kernel 2: single-pass exclusive scan of g_deg -> g_cursor (decoupled lookback)
// ---------------------------------------------------------------------------
#define FLAG_AGG  (1ull << 32)
#define FLAG_INCL (2ull << 32)

__global__ void scan_kernel(int N) {
    int t = threadIdx.x;
    int bid = blockIdx.x;
    int g = bid * 256 + t;
    int lane = t & 31, w = t >> 5;
    int v = (g < N) ? g_deg[g] : 0;
    int incl = v;
    #pragma unroll
    for (int off = 1; off < 32; off <<= 1) {
        int nv = __shfl_up_sync(0xffffffffu, incl, off);
        if (lane >= off) incl += nv;
    }
    __shared__ int wsum[8];
    if (lane == 31) wsum[w] = incl;
    __syncthreads();
    if (t < 8) {
        int xw = wsum[t];
        int in2 = xw;
        #pragma unroll
        for (int off = 1; off < 8; off <<= 1) {
            int nv = __shfl_up_sync(0xffu, in2, off);
            if (t >= off) in2 += nv;
        }
        wsum[t] = in2 - xw;   // exclusive warp offsets
    }
    __syncthreads();
    int excl = incl - v + wsum[w];

    __shared__ int sPrefix;
    __shared__ int sTotal;
    if (t == 255) sTotal = excl + v;
    __syncthreads();
    if (t == 0) {
        unsigned long long total = (unsigned long long)(unsigned)sTotal;
        if (bid == 0) {
            atomicExch(&g_pkt[0], total | FLAG_INCL);
            sPrefix = 0;
        } else {
            atomicExch(&g_pkt[bid], total | FLAG_AGG);
            long long run = 0;
            int j = bid - 1;
            while (true) {
                unsigned long long p;
                do { p = atomicAdd(&g_pkt[j], 0ull); } while ((p >> 32) == 0);
                run += (unsigned)(p & 0xffffffffu);
                if (p & FLAG_INCL) break;
                j--;
            }
            atomicExch(&g_pkt[bid], (total + (unsigned long long)(unsigned)run) | FLAG_INCL);
            sPrefix = (int)run;
        }
    }
    __syncthreads();
    if (g < N) g_cursor[g] = excl + sPrefix;
}

// ---------------------------------------------------------------------------
// Kernel 3: scatter edges into CSR. Per edge: compute e once, accumulate the
// softmax denominator here (scalar atomic), store (s,d) as int2 + e as float.
// Re-zeroes g_pkt for the next replay.
// ---------------------------------------------------------------------------
__global__ void scatter_kernel(const int* __restrict__ ei, int E) {
    int i = blockIdx.x * blockDim.x + threadIdx.x;
    if (i < SCAN_BLOCKS) g_pkt[i] = 0ull;
    if (i >= E) return;
    int s = ei[i];
    int d = ei[E + i];
    float e = __expf(lrelu(__ldg(g_asrc + s) + __ldg(g_adst + d)));
    atomicAdd(&g_denom[d], e);
    int pos = atomicAdd(&g_cursor[d], 1);
    g_cedge[pos] = make_int2(s, d);
    g_e[pos] = e;
}

// ---------------------------------------------------------------------------
// Kernel 4: edge-parallel partials — pure gather + run-dedup + red.v4.
// Each 16-lane group owns 4 consecutive dst-sorted slots: 3 broadcast vector
// loads (2x int4 pairs + 1x float4 e), 4 independent 128B row loads,
// unrolled in-group run merge, ~1.2 red.v4 flushes expected. No MUFU,
// no scalar index loads, no denom atomics.
// ---------------------------------------------------------------------------
__device__ __forceinline__ void flush_run(int d, float4 acc, int l16) {
    float* dst = g_agg + (size_t)d * 64 + l16 * 4;
    asm volatile("red.global.add.v4.f32 [%0], {%1,%2,%3,%4};"
                 :: "l"(dst), "f"(acc.x), "f"(acc.y), "f"(acc.z), "f"(acc.w)
                 : "memory");
}

__global__ __launch_bounds__(512) void edge_kernel(int E) {
    int t = threadIdx.x;
    int grp = t >> 4, l16 = t & 15;
    int base = (blockIdx.x * 32 + grp) * 4;
    if (base >= E) return;
    int rem = E - base;                      // >= 1

    int   s[4], d[4];
    float e[4];
    if (rem >= 4) {
        int4 sd01 = __ldg((const int4*)g_cedge + (base >> 1));
        int4 sd23 = __ldg((const int4*)g_cedge + (base >> 1) + 1);
        float4 ev = __ldg((const float4*)(g_e + base));
        s[0] = sd01.x; d[0] = sd01.y; s[1] = sd01.z; d[1] = sd01.w;
        s[2] = sd23.x; d[2] = sd23.y; s[3] = sd23.z; d[3] = sd23.w;
        e[0] = ev.x; e[1] = ev.y; e[2] = ev.z; e[3] = ev.w;
    } else {
        #pragma unroll
        for (int i = 0; i < 4; i++) {
            if (i < rem) {
                int2 sd = __ldg(g_cedge + base + i);
                s[i] = sd.x; d[i] = sd.y; e[i] = __ldg(g_e + base + i);
            } else {
                s[i] = 0; d[i] = d[i - 1]; e[i] = 0.f;   // merges into prior run, adds 0
            }
        }
    }

    float4 val[4];
    #pragma unroll
    for (int i = 0; i < 4; i++) {
        float2 p = __ldg((const float2*)g_h2 + s[i] * 16 + l16);
        float2 lo = __half22float2(((const __half2*)&p)[0]);
        float2 hi = __half22float2(((const __half2*)&p)[1]);
        val[i] = make_float4(lo.x * e[i], lo.y * e[i], hi.x * e[i], hi.y * e[i]);
    }

    // in-group run merge (branches are uniform across the 16-lane group)
    float4 acc = val[0];
    int    dc  = d[0];
    #pragma unroll
    for (int i = 1; i < 4; i++) {
        if (d[i] == dc) {
            acc.x += val[i].x; acc.y += val[i].y; acc.z += val[i].z; acc.w += val[i].w;
        } else {
            flush_run(dc, acc, l16);
            dc = d[i]; acc = val[i];
        }
    }
    flush_run(dc, acc, l16);
}

// ---------------------------------------------------------------------------
// Kernel 5: streaming finish. Per node: add self-loop term, normalize, +bias,
// relu, accumulate column sums; spread-RED block partials; last block does the
// 64x64 matvec and re-zeroes all replay state (g_deg/g_smulti/g_done).
// ---------------------------------------------------------------------------
__global__ void finish_kernel(const float* __restrict__ bias,
                              const float* __restrict__ W_lin, const float* __restrict__ b_lin,
                              float* __restrict__ out, float invN, int N) {
    __shared__ float sm[64];
    __shared__ float sf[64];
    __shared__ int lastFlag;
    int t = threadIdx.x;
    if (t < 64) sm[t] = 0.f;
    __syncthreads();

    int grp = t >> 4, l16 = t & 15;
    float4 bv = ((const float4*)bias)[l16];
    float4 accS = make_float4(0.f, 0.f, 0.f, 0.f);

    for (int base = blockIdx.x * 16; base < N; base += gridDim.x * 16) {
        int n = base + grp;
        bool act = n < N;
        float asn = 0.f, adn = 0.f, dn = 0.f;
        if (act && l16 == 0) {
            asn = __ldg(g_asrc + n);
            adn = __ldg(g_adst + n);
            dn  = g_denom[n];
            g_deg[n] = 0;                  // cleanup for next replay's histogram
        }
        float es = __expf(lrelu(asn + adn));
        es = __shfl_sync(0xffffffffu, es, 0, 16);
        dn = __shfl_sync(0xffffffffu, dn, 0, 16);
        if (act) {
            float inv = 1.f / (dn + es);
            float4 a = ((const float4*)g_agg)[n * 16 + l16];
            float2 pck = __ldg((const float2*)g_h2 + n * 16 + l16);
            float2 lo = __half22float2(((const __half2*)&pck)[0]);
            float2 hi = __half22float2(((const __half2*)&pck)[1]);
            accS.x += fmaxf((a.x + lo.x * es) * inv + bv.x, 0.f);
            accS.y += fmaxf((a.y + lo.y * es) * inv + bv.y, 0.f);
            accS.z += fmaxf((a.z + hi.x * es) * inv + bv.z, 0.f);
            accS.w += fmaxf((a.w + hi.y * es) * inv + bv.w, 0.f);
        }
    }
    atomicAdd(&sm[l16 * 4 + 0], accS.x);
    atomicAdd(&sm[l16 * 4 + 1], accS.y);
    atomicAdd(&sm[l16 * 4 + 2], accS.z);
    atomicAdd(&sm[l16 * 4 + 3], accS.w);
    __syncthreads();

    if (t < 16) {
        float4 v = *(float4*)&sm[t * 4];
        float* dst = g_smulti + (blockIdx.x & 63) * 64 + t * 4;   // 64-way spread
        asm volatile("red.global.add.v4.f32 [%0], {%1,%2,%3,%4};"
                     :: "l"(dst), "f"(v.x), "f"(v.y), "f"(v.z), "f"(v.w)
                     : "memory");
        __threadfence();
    }
    __syncthreads();
    if (t == 0) {
        int old = atomicAdd(&g_done, 1);
        lastFlag = (old == (int)gridDim.x - 1);
    }
    __syncthreads();

    if (lastFlag) {
        __threadfence();   // acquire: all blocks' reds visible
        if (t < 64) {
            float v = 0.f;
            #pragma unroll 8
            for (int j = 0; j < 64; j++) {
                float pj;
                asm volatile("ld.global.cg.f32 %0, [%1];" : "=f"(pj) : "l"(g_smulti + j * 64 + t));
                v += pj;
                g_smulti[j * 64 + t] = 0.f;   // cleanup for next replay
            }
            sf[t] = v;
        }
        __syncthreads();
        if (t < 64) {
            float acc2 = b_lin[t];
            #pragma unroll 8
            for (int c = 0; c < 64; c++)
                acc2 += (sf[c] * invN) * W_lin[c * 64 + t];
            out[t] = acc2;
        }
        if (t == 0) g_done = 0;               // cleanup for next replay
    }
}

// ---------------------------------------------------------------------------
extern "C" void kernel_launch(void* const* d_in, const int* in_sizes, int n_in,
                              void* d_out, int out_size) {
    const float* x       = (const float*)d_in[0];
    const int*   ei      = (const int*)d_in[1];
    const float* W       = (const float*)d_in[2];
    const float* att_src = (const float*)d_in[3];
    const float* att_dst = (const float*)d_in[4];
    const float* bias    = (const float*)d_in[5];
    const float* W_lin   = (const float*)d_in[6];
    const float* b_lin   = (const float*)d_in[7];

    int N = in_sizes[0] / 128;   // 100000
    int E = in_sizes[1] / 2;     // 1600000
    int GB = (N + 63) / 64;      // gemm blocks
    int HB = (E + 255) / 256;    // hist blocks
    int ZB = (N * 16 + N / 4 + 255) / 256;   // zero blocks (g_agg + g_denom in float4)

    gemm_hist_zero_kernel<<<GB + HB + ZB, 256>>>(x, W, att_src, att_dst, ei, N, E, GB, HB);
    scan_kernel<<<(N + 255) / 256, 256>>>(N);
    scatter_kernel<<<(E + 255) / 256, 256>>>(ei, E);
    edge_kernel<<<(E + 127) / 128, 512>>>(E);
    finish_kernel<<<1184, 256>>>(bias, W_lin, b_lin, (float*)d_out, 1.0f / (float)N, N);
}

// round 15
// speedup vs baseline: 1.2500x; 1.2500x over previous
#include <cuda_runtime.h>
#include <cuda_fp16.h>

// ---------------------------------------------------------------------------
// DummyGAT: h = x@W; GAT edge softmax + aggregation; out = mean(relu(agg)@W_lin + b_lin)
// N = 100000 nodes, E = 1.6M edges, IN=128, HID=64, OUT=64
// 5 launches: [hmma-gemm+hist+zero] -> [scan] -> [scatter] -> [edge RED] -> [finish]
// GEMM runs on tensor cores (fp16 in, fp32 accum). CSR slot packed as one int4.
// Denominator accumulated at edge run-flush (deduped atomics).
// ---------------------------------------------------------------------------

#define N_MAX 100000
#define E_MAX 1600000
#define SCAN_BLOCKS 391   // ceil(100000/256)

__device__ __align__(256) __half g_h2[N_MAX * 64];    // h in fp16 (gather operand)
__device__ __align__(256) float  g_asrc[N_MAX];
__device__ __align__(256) float  g_adst[N_MAX];
__device__ __align__(256) float  g_agg[N_MAX * 64];   // edge-sum accumulator (zeroed in K1)
__device__ __align__(256) float  g_denom[N_MAX];      // edge exp-sum (zeroed in K1, filled by edge)
__device__ __align__(256) int    g_deg[N_MAX];        // in-degree (zeroed by finish)
__device__ __align__(256) int    g_cursor[N_MAX];     // scan result / scatter cursor
__device__ __align__(256) int4   g_cslot[E_MAX];      // CSR slot: {src, dst, e_bits, 0}
__device__ __align__(256) unsigned long long g_pkt[SCAN_BLOCKS]; // lookback, zeroed by scatter
__device__ __align__(256) float  g_smulti[64 * 64];   // spread node-sum slots (zeroed by finish)
__device__ int g_done;                                // zeroed by finish

__device__ __forceinline__ float lrelu(float x) { return x > 0.f ? x : 0.2f * x; }

// ---------------------------------------------------------------------------
// Kernel 1: three block partitions.
//  [0,GB): h = x@W on TENSOR cores (fp16 inputs, fp32 accum) + attention scores
//  [GB,GB+HB): in-degree histogram
//  [GB+HB,..): zero g_agg and g_denom
// GEMM tile: 128 rows x 64 cols, K staged in 2 chunks of 64.
// 8 warps: warp_m = wid%4 (32 rows), warp_n = wid/4 (32 cols).
// ---------------------------------------------------------------------------
__global__ __launch_bounds__(256) void gemm_hist_zero_kernel(
        const float* __restrict__ x, const float* __restrict__ W,
        const float* __restrict__ att_src, const float* __restrict__ att_dst,
        const int* __restrict__ ei, int N, int E, int GB, int HB) {
    if (blockIdx.x >= GB + HB) {          // ---- zero partition ----
        int i = (blockIdx.x - GB - HB) * 256 + threadIdx.x;
        int nAgg = N * 16;                // g_agg in float4 units
        if (i < nAgg) ((float4*)g_agg)[i] = make_float4(0.f, 0.f, 0.f, 0.f);
        else if (i - nAgg < N / 4) ((float4*)g_denom)[i - nAgg] = make_float4(0.f, 0.f, 0.f, 0.f);
        return;
    }
    if (blockIdx.x >= GB) {               // ---- histogram partition ----
        int i = (blockIdx.x - GB) * 256 + threadIdx.x;
        if (i < E) atomicAdd(&g_deg[ei[E + i]], 1);
        return;
    }
    // ---- gemm partition ----
    __shared__ __half xs[128 * 72];   // x tile (chunk): 128 rows x 64 k (+8 pad); reused as h tile
    __shared__ __half wsm[64 * 72];   // W chunk: 64 k x 64 n (+8 pad)
    __shared__ float  s_as[64], s_ad[64];

    int t = threadIdx.x;
    int row0 = blockIdx.x * 128;
    int wid = t >> 5, lane = t & 31;
    int warp_m = wid & 3, warp_n = wid >> 2;
    int m0 = warp_m * 32, n0 = warp_n * 32;

    if (t < 64) { s_as[t] = att_src[t]; s_ad[t] = att_dst[t]; }

    float acc[2][4][4];
    #pragma unroll
    for (int a = 0; a < 2; a++)
        #pragma unroll
        for (int b = 0; b < 4; b++)
            #pragma unroll
            for (int c = 0; c < 4; c++) acc[a][b][c] = 0.f;

    unsigned xs_base = (unsigned)__cvta_generic_to_shared(xs);
    unsigned ws_base = (unsigned)__cvta_generic_to_shared(wsm);

    for (int chunk = 0; chunk < 2; chunk++) {
        int k0 = chunk * 64;
        // load x chunk: 128 rows x 64 k = 2048 float4 -> fp16
        #pragma unroll
        for (int i = 0; i < 8; i++) {
            int idx = t + i * 256;
            int r = idx >> 4, c4 = idx & 15;
            int grow = row0 + r;
            float4 v = make_float4(0.f, 0.f, 0.f, 0.f);
            if (grow < N) v = ((const float4*)x)[grow * 32 + (k0 >> 2) + c4];
            __half2 h01 = __floats2half2_rn(v.x, v.y);
            __half2 h23 = __floats2half2_rn(v.z, v.w);
            *(__half2*)&xs[r * 72 + c4 * 4] = h01;
            *(__half2*)&xs[r * 72 + c4 * 4 + 2] = h23;
        }
        // load W chunk: 64 k x 64 n = 1024 float4 -> fp16
        #pragma unroll
        for (int i = 0; i < 4; i++) {
            int idx = t + i * 256;
            int r = idx >> 4, c4 = idx & 15;
            float4 v = ((const float4*)(W + k0 * 64))[idx];
            __half2 h01 = __floats2half2_rn(v.x, v.y);
            __half2 h23 = __floats2half2_rn(v.z, v.w);
            *(__half2*)&wsm[r * 72 + c4 * 4] = h01;
            *(__half2*)&wsm[r * 72 + c4 * 4 + 2] = h23;
        }
        __syncthreads();

        #pragma unroll
        for (int ks = 0; ks < 4; ks++) {
            int kk = ks * 16;
            // A fragments (2 m-tiles)
            unsigned a0[2], a1[2], a2[2], a3[2];
            #pragma unroll
            for (int mt = 0; mt < 2; mt++) {
                int tile = lane >> 3, rit = lane & 7;
                int arow = m0 + mt * 16 + (tile & 1) * 8 + rit;
                int acol = kk + (tile >> 1) * 8;
                unsigned addr = xs_base + (arow * 72 + acol) * 2;
                asm volatile("ldmatrix.sync.aligned.m8n8.x4.shared.b16 {%0,%1,%2,%3}, [%4];"
                             : "=r"(a0[mt]), "=r"(a1[mt]), "=r"(a2[mt]), "=r"(a3[mt]) : "r"(addr));
            }
            // B fragments (4 n-tiles) + mma
            #pragma unroll
            for (int nt = 0; nt < 4; nt++) {
                int tile = (lane >> 3) & 1, rit = lane & 7;
                int brow = kk + tile * 8 + rit;
                int bcol = n0 + nt * 8;
                unsigned baddr = ws_base + (brow * 72 + bcol) * 2;
                unsigned b0, b1;
                asm volatile("ldmatrix.sync.aligned.m8n8.x2.trans.shared.b16 {%0,%1}, [%2];"
                             : "=r"(b0), "=r"(b1) : "r"(baddr));
                #pragma unroll
                for (int mt = 0; mt < 2; mt++) {
                    asm volatile(
                        "mma.sync.aligned.m16n8k16.row.col.f32.f16.f16.f32 "
                        "{%0,%1,%2,%3}, {%4,%5,%6,%7}, {%8,%9}, {%0,%1,%2,%3};"
                        : "+f"(acc[mt][nt][0]), "+f"(acc[mt][nt][1]),
                          "+f"(acc[mt][nt][2]), "+f"(acc[mt][nt][3])
                        : "r"(a0[mt]), "r"(a1[mt]), "r"(a2[mt]), "r"(a3[mt]),
                          "r"(b0), "r"(b1));
                }
            }
        }
        __syncthreads();
    }

    // ---- epilogue: store h tile (fp16) into xs, then scores + global writes ----
    int groupID = lane >> 2, tid4 = lane & 3;
    #pragma unroll
    for (int mt = 0; mt < 2; mt++) {
        #pragma unroll
        for (int nt = 0; nt < 4; nt++) {
            int r = m0 + mt * 16 + groupID;
            int c = n0 + nt * 8 + tid4 * 2;
            *(__half2*)&xs[r * 72 + c]       = __floats2half2_rn(acc[mt][nt][0], acc[mt][nt][1]);
            *(__half2*)&xs[(r + 8) * 72 + c] = __floats2half2_rn(acc[mt][nt][2], acc[mt][nt][3]);
        }
    }
    __syncthreads();

    // scores: threads 0..127, one row each
    if (t < 128) {
        int r = row0 + t;
        if (r < N) {
            float pa = 0.f, pd = 0.f;
            #pragma unroll 16
            for (int j = 0; j < 32; j++) {
                float2 f = __half22float2(*(__half2*)&xs[t * 72 + j * 2]);
                pa += f.x * s_as[j * 2] + f.y * s_as[j * 2 + 1];
                pd += f.x * s_ad[j * 2] + f.y * s_ad[j * 2 + 1];
            }
            g_asrc[r] = pa;
            g_adst[r] = pd;
        }
    }
    // copy h tile to g_h2: 2048 uint2 (8B each)
    #pragma unroll
    for (int i = 0; i < 8; i++) {
        int idx = t + i * 256;
        int r = idx >> 4, seg = idx & 15;
        int grow = row0 + r;
        if (grow < N) {
            uint2 v = *(uint2*)&xs[r * 72 + seg * 4];
            ((uint2*)g_h2)[grow * 16 + seg] = v;
        }
    }
}

// ---------------------------------------------------------------------------
// Kernel 2: single-pass exclusive scan of g_deg -> g_cursor (decoupled lookback)
// ---------------------------------------------------------------------------
#define FLAG_AGG  (1ull << 32)
#define FLAG_INCL (2ull << 32)

__global__ void scan_kernel(int N) {
    int t = threadIdx.x;
    int bid = blockIdx.x;
    int g = bid * 256 + t;
    int lane = t & 31, w = t >> 5;
    int v = (g < N) ? g_deg[g] : 0;
    int incl = v;
    #pragma unroll
    for (int off = 1; off < 32; off <<= 1) {
        int nv = __shfl_up_sync(0xffffffffu, incl, off);
        if (lane >= off) incl += nv;
    }
    __shared__ int wsum[8];
    if (lane == 31) wsum[w] = incl;
    __syncthreads();
    if (t < 8) {
        int xw = wsum[t];
        int in2 = xw;
        #pragma unroll
        for (int off = 1; off < 8; off <<= 1) {
            int nv = __shfl_up_sync(0xffu, in2, off);
            if (t >= off) in2 += nv;
        }
        wsum[t] = in2 - xw;   // exclusive warp offsets
    }
    __syncthreads();
    int excl = incl - v + wsum[w];

    __shared__ int sPrefix;
    __shared__ int sTotal;
    if (t == 255) sTotal = excl + v;
    __syncthreads();
    if (t == 0) {
        unsigned long long total = (unsigned long long)(unsigned)sTotal;
        if (bid == 0) {
            atomicExch(&g_pkt[0], total | FLAG_INCL);
            sPrefix = 0;
        } else {
            atomicExch(&g_pkt[bid], total | FLAG_AGG);
            long long run = 0;
            int j = bid - 1;
            while (true) {
                unsigned long long p;
                do { p = atomicAdd(&g_pkt[j], 0ull); } while ((p >> 32) == 0);
                run += (unsigned)(p & 0xffffffffu);
                if (p & FLAG_INCL) break;
                j--;
            }
            atomicExch(&g_pkt[bid], (total + (unsigned long long)(unsigned)run) | FLAG_INCL);
            sPrefix = (int)run;
        }
    }
    __syncthreads();
    if (g < N) g_cursor[g] = excl + sPrefix;
}

// ---------------------------------------------------------------------------
// Kernel 3: scatter edges into CSR. Per edge: compute e once, pack the slot as
// one int4 {s, d, e_bits, 0} -> single STG.128 (1 sector). Re-zero g_pkt.
// ---------------------------------------------------------------------------
__global__ void scatter_kernel(const int* __restrict__ ei, int E) {
    int i = blockIdx.x * blockDim.x + threadIdx.x;
    if (i < SCAN_BLOCKS) g_pkt[i] = 0ull;
    if (i >= E) return;
    int s = ei[i];
    int d = ei[E + i];
    float e = __expf(lrelu(__ldg(g_asrc + s) + __ldg(g_adst + d)));
    int pos = atomicAdd(&g_cursor[d], 1);
    g_cslot[pos] = make_int4(s, d, __float_as_int(e), 0);
}

// ---------------------------------------------------------------------------
// Kernel 4: edge-parallel partials. Each 16-lane group owns 4 consecutive
// dst-sorted slots: 4 consecutive int4 broadcast loads, 4 independent 128B
// row loads, unrolled run merge; flush = red.v4 + (lane0) denom atomic.
// ---------------------------------------------------------------------------
__device__ __forceinline__ void flush_run(int d, float4 acc, float ea, int l16) {
    float* dst = g_agg + (size_t)d * 64 + l16 * 4;
    asm volatile("red.global.add.v4.f32 [%0], {%1,%2,%3,%4};"
                 :: "l"(dst), "f"(acc.x), "f"(acc.y), "f"(acc.z), "f"(acc.w)
                 : "memory");
    if (l16 == 0) atomicAdd(&g_denom[d], ea);
}

__global__ __launch_bounds__(512) void edge_kernel(int E) {
    int t = threadIdx.x;
    int grp = t >> 4, l16 = t & 15;
    int base = (blockIdx.x * 32 + grp) * 4;
    if (base >= E) return;
    int rem = E - base;                      // >= 1

    int   s[4], d[4];
    float e[4];
    #pragma unroll
    for (int i = 0; i < 4; i++) {
        if (i < rem) {
            int4 q = __ldg(g_cslot + base + i);
            s[i] = q.x; d[i] = q.y; e[i] = __int_as_float(q.z);
        } else {
            s[i] = 0; d[i] = d[i - 1]; e[i] = 0.f;   // merges into prior run, adds 0
        }
    }

    float4 val[4];
    #pragma unroll
    for (int i = 0; i < 4; i++) {
        float2 p = __ldg((const float2*)g_h2 + s[i] * 16 + l16);
        float2 lo = __half22float2(((const __half2*)&p)[0]);
        float2 hi = __half22float2(((const __half2*)&p)[1]);
        val[i] = make_float4(lo.x * e[i], lo.y * e[i], hi.x * e[i], hi.y * e[i]);
    }

    // in-group run merge (branches are uniform across the 16-lane group)
    float4 acc = val[0];
    float  ea  = e[0];
    int    dc  = d[0];
    #pragma unroll
    for (int i = 1; i < 4; i++) {
        if (d[i] == dc) {
            acc.x += val[i].x; acc.y += val[i].y; acc.z += val[i].z; acc.w += val[i].w;
            ea += e[i];
        } else {
            flush_run(dc, acc, ea, l16);
            dc = d[i]; acc = val[i]; ea = e[i];
        }
    }
    flush_run(dc, acc, ea, l16);
}

// ---------------------------------------------------------------------------
// Kernel 5: streaming finish. Per node: add self-loop term, normalize, +bias,
// relu, accumulate column sums; spread-RED block partials; last block does the
// 64x64 matvec and re-zeroes all replay state (g_deg/g_smulti/g_done).
// ---------------------------------------------------------------------------
__global__ void finish_kernel(const float* __restrict__ bias,
                              const float* __restrict__ W_lin, const float* __restrict__ b_lin,
                              float* __restrict__ out, float invN, int N) {
    __shared__ float sm[64];
    __shared__ float sf[64];
    __shared__ int lastFlag;
    int t = threadIdx.x;
    if (t < 64) sm[t] = 0.f;
    __syncthreads();

    int grp = t >> 4, l16 = t & 15;
    float4 bv = ((const float4*)bias)[l16];
    float4 accS = make_float4(0.f, 0.f, 0.f, 0.f);

    for (int base = blockIdx.x * 16; base < N; base += gridDim.x * 16) {
        int n = base + grp;
        bool act = n < N;
        float asn = 0.f, adn = 0.f, dn = 0.f;
        if (act && l16 == 0) {
            asn = __ldg(g_asrc + n);
            adn = __ldg(g_adst + n);
            dn  = g_denom[n];
            g_deg[n] = 0;                  // cleanup for next replay's histogram
        }
        float es = __expf(lrelu(asn + adn));
        es = __shfl_sync(0xffffffffu, es, 0, 16);
        dn = __shfl_sync(0xffffffffu, dn, 0, 16);
        if (act) {
            float inv = 1.f / (dn + es);
            float4 a = ((const float4*)g_agg)[n * 16 + l16];
            float2 pck = __ldg((const float2*)g_h2 + n * 16 + l16);
            float2 lo = __half22float2(((const __half2*)&pck)[0]);
            float2 hi = __half22float2(((const __half2*)&pck)[1]);
            accS.x += fmaxf((a.x + lo.x * es) * inv + bv.x, 0.f);
            accS.y += fmaxf((a.y + lo.y * es) * inv + bv.y, 0.f);
            accS.z += fmaxf((a.z + hi.x * es) * inv + bv.z, 0.f);
            accS.w += fmaxf((a.w + hi.y * es) * inv + bv.w, 0.f);
        }
    }
    atomicAdd(&sm[l16 * 4 + 0], accS.x);
    atomicAdd(&sm[l16 * 4 + 1], accS.y);
    atomicAdd(&sm[l16 * 4 + 2], accS.z);
    atomicAdd(&sm[l16 * 4 + 3], accS.w);
    __syncthreads();

    if (t < 16) {
        float4 v = *(float4*)&sm[t * 4];
        float* dst = g_smulti + (blockIdx.x & 63) * 64 + t * 4;   // 64-way spread
        asm volatile("red.global.add.v4.f32 [%0], {%1,%2,%3,%4};"
                     :: "l"(dst), "f"(v.x), "f"(v.y), "f"(v.z), "f"(v.w)
                     : "memory");
        __threadfence();
    }
    __syncthreads();
    if (t == 0) {
        int old = atomicAdd(&g_done, 1);
        lastFlag = (old == (int)gridDim.x - 1);
    }
    __syncthreads();

    if (lastFlag) {
        __threadfence();   // acquire: all blocks' reds visible
        if (t < 64) {
            float v = 0.f;
            #pragma unroll 8
            for (int j = 0; j < 64; j++) {
                float pj;
                asm volatile("ld.global.cg.f32 %0, [%1];" : "=f"(pj) : "l"(g_smulti + j * 64 + t));
                v += pj;
                g_smulti[j * 64 + t] = 0.f;   // cleanup for next replay
            }
            sf[t] = v;
        }
        __syncthreads();
        if (t < 64) {
            float acc2 = b_lin[t];
            #pragma unroll 8
            for (int c = 0; c < 64; c++)
                acc2 += (sf[c] * invN) * W_lin[c * 64 + t];
            out[t] = acc2;
        }
        if (t == 0) g_done = 0;               // cleanup for next replay
    }
}

// ---------------------------------------------------------------------------
extern "C" void kernel_launch(void* const* d_in, const int* in_sizes, int n_in,
                              void* d_out, int out_size) {
    const float* x       = (const float*)d_in[0];
    const int*   ei      = (const int*)d_in[1];
    const float* W       = (const float*)d_in[2];
    const float* att_src = (const float*)d_in[3];
    const float* att_dst = (const float*)d_in[4];
    const float* bias    = (const float*)d_in[5];
    const float* W_lin   = (const float*)d_in[6];
    const float* b_lin   = (const float*)d_in[7];

    int N = in_sizes[0] / 128;   // 100000
    int E = in_sizes[1] / 2;     // 1600000
    int GB = (N + 127) / 128;    // gemm blocks (128-row tiles)
    int HB = (E + 255) / 256;    // hist blocks
    int ZB = (N * 16 + N / 4 + 255) / 256;   // zero blocks (g_agg + g_denom in float4)

    gemm_hist_zero_kernel<<<GB + HB + ZB, 256>>>(x, W, att_src, att_dst, ei, N, E, GB, HB);
    scan_kernel<<<(N + 255) / 256, 256>>>(N);
    scatter_kernel<<<(E + 255) / 256, 256>>>(ei, E);
    edge_kernel<<<(E + 127) / 128, 512>>>(E);
    finish_kernel<<<1184, 256>>>(bias, W_lin, b_lin, (float*)d_out, 1.0f / (float)N, N);
}